// round 13
// baseline (speedup 1.0000x reference)
#include <cuda_runtime.h>
#include <cstdint>

#define N_NODES 50000
#define N_EDGES 800000
#define H 64
#define RES 0.5f
#define INV_1PRES (1.0f / (1.0f + RES))

#define XS2_STRIDE 36   // uint2 stride: A-pair LDS.64 conflict-free per phase
#define WP_STRIDE  64   // uint2 stride: B-pair LDS.64 conflict-free via j^(4q) swizzle

// ---------------- device scratch (no allocation allowed) ----------------
__device__ float g_s1[N_NODES];
__device__ float g_s2[N_NODES];      // att_b folded in
__device__ float g_rowsum[N_NODES];
__device__ float g_expatt[N_EDGES];

__device__ __forceinline__ uint32_t cvt_tf32(float x) {
    uint32_t r;
    asm("cvt.rna.tf32.f32 %0, %1;" : "=r"(r) : "f"(x));
    return r;
}

__device__ __forceinline__ void mma_tf32(float c[4], const uint32_t a[4],
                                         uint32_t b0, uint32_t b1) {
    asm volatile(
        "mma.sync.aligned.m16n8k8.row.col.f32.tf32.tf32.f32 "
        "{%0,%1,%2,%3}, {%4,%5,%6,%7}, {%8,%9}, {%0,%1,%2,%3};"
        : "+f"(c[0]), "+f"(c[1]), "+f"(c[2]), "+f"(c[3])
        : "r"(a[0]), "r"(a[1]), "r"(a[2]), "r"(a[3]), "r"(b0), "r"(b1));
}

// ------------------------------------------------------------------------
// Kernel 1: per-node attention scalars via tensor-core tf32 MMA.
//   smem holds tf32 bits in PAIR-INTERLEAVED layout: entry (kk*4+q) of a
//   row is uint2{elem[8kk+q], elem[8kk+q+4]} -> every fragment load in the
//   mainloop is ONE LDS.64 (A: 2/step, B: 2/jt) instead of two LDS.32.
//   W pairs column-swizzled j^(4q) so each 16-lane phase hits 16 banks.
//   Block(256)=8 warps, 128-node tile; warp w owns nodes w*16..w*16+15.
// ------------------------------------------------------------------------
__global__ __launch_bounds__(256)
void gat_node_kernel(const float* __restrict__ embeds,
                     const float* __restrict__ W1, const float* __restrict__ b1,
                     const float* __restrict__ W2, const float* __restrict__ b2,
                     const float* __restrict__ att_w, const float* __restrict__ att_b) {
    extern __shared__ uint2 smem2[];
    uint2* Xs2 = smem2;                        // [128][XS2_STRIDE]
    uint2* W1p = smem2 + 128 * XS2_STRIDE;     // [32][WP_STRIDE] (pairs, swizzled)
    uint2* W2p = W1p + 32 * WP_STRIDE;

    const int tid  = threadIdx.x;
    const int warp = tid >> 5;
    const int lane = tid & 31;
    const int g    = lane >> 2;   // fragment row
    const int q    = lane & 3;    // k / col-pair selector
    const int q4   = q * 4;
    const int tile = blockIdx.x * 128;

    // ---- load W1, W2: cvt once, pair-interleave + swizzle ----
    // element [k][j] -> pair row kp=(k>>3)*4+(k&3), half h=(k>>2)&1,
    // column (j) ^ (4*(k&3)).
#pragma unroll
    for (int i = 0; i < 4; i++) {
        int idx = tid + i * 256;            // [0,1024): 64 rows x 16 float4
        int k  = idx >> 4;
        int j4 = idx & 15;
        float4 v1 = __ldg((const float4*)(W1 + k * H) + j4);
        float4 v2 = __ldg((const float4*)(W2 + k * H) + j4);
        int kp = (k >> 3) * 4 + (k & 3);
        int h  = (k >> 2) & 1;
        int jb = (j4 * 4) ^ ((k & 3) * 4);      // 4-aligned block, bits0-1 free
        uint32_t* d1 = (uint32_t*)(W1p + kp * WP_STRIDE + jb) + h;
        uint32_t* d2 = (uint32_t*)(W2p + kp * WP_STRIDE + jb) + h;
        d1[0] = cvt_tf32(v1.x); d1[2] = cvt_tf32(v1.y);
        d1[4] = cvt_tf32(v1.z); d1[6] = cvt_tf32(v1.w);
        d2[0] = cvt_tf32(v2.x); d2[2] = cvt_tf32(v2.y);
        d2[4] = cvt_tf32(v2.z); d2[6] = cvt_tf32(v2.w);
    }
    // ---- load X tile: cvt once, pair-interleave ----
    // float4 chunk k4 covers k=4k4..4k4+3: kk=k4>>1, h=k4&1, q=t.
#pragma unroll
    for (int i = 0; i < 8; i++) {
        int idx = tid + i * 256;            // [0,2048): 128 rows x 16 float4
        int nl = idx >> 4;
        int k4 = idx & 15;
        int node = tile + nl;
        if (node > N_NODES - 1) node = N_NODES - 1;
        float4 v = __ldg((const float4*)(embeds + (size_t)node * H) + k4);
        int kpb = (k4 >> 1) * 4;
        int h   = k4 & 1;
        uint32_t* d = (uint32_t*)(Xs2 + nl * XS2_STRIDE + kpb) + h;
        d[0] = cvt_tf32(v.x); d[2] = cvt_tf32(v.y);
        d[4] = cvt_tf32(v.z); d[6] = cvt_tf32(v.w);
    }
    __syncthreads();

    // ---- MMA mainloop: LDS.64 fragments + MMA, conflict-free ----
    float C1[8][4], C2[8][4];
#pragma unroll
    for (int jt = 0; jt < 8; jt++)
#pragma unroll
        for (int r = 0; r < 4; r++) { C1[jt][r] = 0.f; C2[jt][r] = 0.f; }

    const uint2* xr0 = Xs2 + (warp * 16 + g) * XS2_STRIDE;
    const uint2* xr8 = xr0 + 8 * XS2_STRIDE;

#pragma unroll
    for (int kk = 0; kk < 8; kk++) {
        int kq = kk * 4 + q;
        uint2 a0 = xr0[kq];
        uint2 a8 = xr8[kq];
        uint32_t A[4];
        A[0] = a0.x; A[1] = a8.x; A[2] = a0.y; A[3] = a8.y;
        const uint2* w1r = W1p + kq * WP_STRIDE;
        const uint2* w2r = W2p + kq * WP_STRIDE;
#pragma unroll
        for (int jt = 0; jt < 8; jt++) {
            int jb = (jt * 8 + g) ^ q4;     // unswizzle
            uint2 bA = w1r[jb];
            uint2 bB = w2r[jb];
            mma_tf32(C1[jt], A, bA.x, bA.y);
            mma_tf32(C2[jt], A, bB.x, bB.y);
        }
    }

    // ---- epilogue: bias + relu + att_w dot, in-fragment ----
    float p1lo = 0.f, p1hi = 0.f, p2lo = 0.f, p2hi = 0.f;
#pragma unroll
    for (int jt = 0; jt < 8; jt++) {
        int c0 = jt * 8 + q * 2;
        float bb0 = __ldg(b1 + c0),      bb1 = __ldg(b1 + c0 + 1);
        float aw0 = __ldg(att_w + c0),   aw1 = __ldg(att_w + c0 + 1);
        p1lo += fmaxf(C1[jt][0] + bb0, 0.f) * aw0 + fmaxf(C1[jt][1] + bb1, 0.f) * aw1;
        p1hi += fmaxf(C1[jt][2] + bb0, 0.f) * aw0 + fmaxf(C1[jt][3] + bb1, 0.f) * aw1;
        bb0 = __ldg(b2 + c0);            bb1 = __ldg(b2 + c0 + 1);
        aw0 = __ldg(att_w + H + c0);     aw1 = __ldg(att_w + H + c0 + 1);
        p2lo += fmaxf(C2[jt][0] + bb0, 0.f) * aw0 + fmaxf(C2[jt][1] + bb1, 0.f) * aw1;
        p2hi += fmaxf(C2[jt][2] + bb0, 0.f) * aw0 + fmaxf(C2[jt][3] + bb1, 0.f) * aw1;
    }
#pragma unroll
    for (int m = 1; m <= 2; m <<= 1) {
        p1lo += __shfl_xor_sync(0xffffffffu, p1lo, m);
        p1hi += __shfl_xor_sync(0xffffffffu, p1hi, m);
        p2lo += __shfl_xor_sync(0xffffffffu, p2lo, m);
        p2hi += __shfl_xor_sync(0xffffffffu, p2hi, m);
    }

    if (q == 0) {
        float ab = __ldg(att_b);
        int node = tile + warp * 16 + g;
        if (node < N_NODES) {
            g_s1[node] = p1lo;
            g_s2[node] = p2lo + ab;
        }
        if (node + 8 < N_NODES) {
            g_s1[node + 8] = p1hi;
            g_s2[node + 8] = p2hi + ab;
        }
    }

    if (tid < 128) {
        int node = tile + tid;
        if (node < N_NODES) g_rowsum[node] = 0.f;
    }
}

// ------------------------------------------------------------------------
// Kernel 2: per-edge exp(att) + segment-sum; also zeroes out_part
// (exactly one float4 per thread: 800k threads x 4 = 3.2M floats = N*H).
// ------------------------------------------------------------------------
__global__ __launch_bounds__(256)
void gat_edge_att_kernel(const int* __restrict__ edge_index,
                         float* __restrict__ out_part) {
    int e = blockIdx.x * blockDim.x + threadIdx.x;
    if (e >= N_EDGES) return;

    ((float4*)out_part)[e] = make_float4(0.f, 0.f, 0.f, 0.f);

    int r = __ldg(edge_index + e);
    int c = __ldg(edge_index + N_EDGES + e);
    float ea = __expf(__ldg(g_s1 + r) + __ldg(g_s2 + c));
    g_expatt[e] = ea;
    atomicAdd(&g_rowsum[r], ea);
}

// ------------------------------------------------------------------------
// Kernel 3: per-edge value + SpMM scatter (16 threads/edge, float4 red).
// ------------------------------------------------------------------------
__global__ __launch_bounds__(256)
void gat_edge_spmm_kernel(const int* __restrict__ edge_index,
                          const float* __restrict__ adj_values,
                          const float* __restrict__ embeds,
                          float* __restrict__ values,
                          float* __restrict__ out_part) {
    unsigned gid = blockIdx.x * blockDim.x + threadIdx.x;
    unsigned e = gid >> 4;
    if (e >= N_EDGES) return;
    unsigned sub = gid & 15u;

    int r = __ldg(edge_index + e);
    int c = __ldg(edge_index + N_EDGES + e);
    float ea = __ldg(g_expatt + e);
    float rs = __ldg(g_rowsum + r) + 1e-6f;
    float v = fmaf(RES, __ldg(adj_values + e), __fdividef(ea, rs)) * INV_1PRES;
    if (sub == 0) values[e] = v;

    float4 ev = __ldg((const float4*)(embeds + (size_t)c * H + sub * 4));
    float* dst = out_part + (size_t)r * H + sub * 4;
    asm volatile("red.global.add.v4.f32 [%0], {%1, %2, %3, %4};"
                 :: "l"(dst), "f"(ev.x * v), "f"(ev.y * v), "f"(ev.z * v), "f"(ev.w * v)
                 : "memory");
}

// ------------------------------------------------------------------------
extern "C" void kernel_launch(void* const* d_in, const int* in_sizes, int n_in,
                              void* d_out, int out_size) {
    const int*   edge_index = (const int*)d_in[0];
    const float* adj_values = (const float*)d_in[1];
    const float* embeds     = (const float*)d_in[2];
    const float* W1         = (const float*)d_in[3];
    const float* b1         = (const float*)d_in[4];
    const float* W2         = (const float*)d_in[5];
    const float* b2         = (const float*)d_in[6];
    const float* att_w      = (const float*)d_in[7];
    const float* att_b      = (const float*)d_in[8];

    float* values   = (float*)d_out;            // [E]
    float* out_part = (float*)d_out + N_EDGES;  // [N, H]

    // Xs2: 128*36 uint2 = 36864B; W1p/W2p: 32*64 uint2 = 16384B each.
    const int smem_bytes = (128 * XS2_STRIDE + 2 * 32 * WP_STRIDE) * 8;  // 69632

    static bool attr_done = false;
    if (!attr_done) {
        cudaFuncSetAttribute(gat_node_kernel,
                             cudaFuncAttributeMaxDynamicSharedMemorySize, smem_bytes);
        attr_done = true;
    }

    gat_node_kernel<<<(N_NODES + 127) / 128, 256, smem_bytes>>>(
        embeds, W1, b1, W2, b2, att_w, att_b);

    gat_edge_att_kernel<<<(N_EDGES + 255) / 256, 256>>>(edge_index, out_part);

    gat_edge_spmm_kernel<<<(N_EDGES * 16 + 255) / 256, 256>>>(
        edge_index, adj_values, embeds, values, out_part);
}

// round 14
// speedup vs baseline: 1.0680x; 1.0680x over previous
#include <cuda_runtime.h>
#include <cstdint>

#define N_NODES 50000
#define N_EDGES 800000
#define H 64
#define RES 0.5f
#define INV_1PRES (1.0f / (1.0f + RES))

#define XS_STRIDE 68   // padded: A-frag LDS conflict-free (4g+q spans banks)
#define WS_STRIDE 64   // XOR-swizzled: B-frag LDS conflict-free, no pad needed

// ---------------- device scratch (no allocation allowed) ----------------
__device__ float g_s1[N_NODES];
__device__ float g_s2[N_NODES];      // att_b folded in
__device__ float g_rowsum[N_NODES];
__device__ float g_expatt[N_EDGES];

__device__ __forceinline__ uint32_t cvt_tf32(float x) {
    uint32_t r;
    asm("cvt.rna.tf32.f32 %0, %1;" : "=r"(r) : "f"(x));
    return r;
}

__device__ __forceinline__ void mma_tf32(float c[4], const uint32_t a[4],
                                         uint32_t b0, uint32_t b1) {
    asm volatile(
        "mma.sync.aligned.m16n8k8.row.col.f32.tf32.tf32.f32 "
        "{%0,%1,%2,%3}, {%4,%5,%6,%7}, {%8,%9}, {%0,%1,%2,%3};"
        : "+f"(c[0]), "+f"(c[1]), "+f"(c[2]), "+f"(c[3])
        : "r"(a[0]), "r"(a[1]), "r"(a[2]), "r"(a[3]), "r"(b0), "r"(b1));
}

// ------------------------------------------------------------------------
// Kernel 1: per-node attention scalars via tensor-core tf32 MMA.
//   TWO-PASS over W1/W2 reusing ONE 32-reg C array -> regs fit 3 blocks/SM
//   (grid 391 = single wave at 3 blocks/SM, 24 warps/SM hides load latency).
//   smem holds PRE-CONVERTED tf32 bits; W tiles XOR-swizzled so A and B
//   fragment LDS are conflict-free. Block(256)=8 warps, 128-node tile.
// ------------------------------------------------------------------------
__global__ __launch_bounds__(256, 3)
void gat_node_kernel(const float* __restrict__ embeds,
                     const float* __restrict__ W1, const float* __restrict__ b1,
                     const float* __restrict__ W2, const float* __restrict__ b2,
                     const float* __restrict__ att_w, const float* __restrict__ att_b) {
    extern __shared__ uint32_t smem_u[];
    uint32_t* Xs  = smem_u;                              // [128][XS_STRIDE]
    uint32_t* W1s = smem_u + 128 * XS_STRIDE;            // [64][WS_STRIDE] swizzled
    uint32_t* W2s = W1s + 64 * WS_STRIDE;

    const int tid  = threadIdx.x;
    const int warp = tid >> 5;
    const int lane = tid & 31;
    const int g    = lane >> 2;   // fragment row
    const int q    = lane & 3;    // k / col-pair selector
    const int tile = blockIdx.x * 128;

    // ---- load W1, W2: cvt to tf32 once, store bits with XOR swizzle ----
#pragma unroll
    for (int i = 0; i < 4; i++) {
        int idx = tid + i * 256;            // [0,1024): 64 rows x 16 float4
        int k  = idx >> 4;
        int j4 = idx & 15;
        float4 v1 = __ldg((const float4*)(W1 + k * H) + j4);
        float4 v2 = __ldg((const float4*)(W2 + k * H) + j4);
        int jcol = (j4 * 4) ^ ((k & 3) * 8);    // swizzled column (4-aligned)
        uint32_t* d1 = W1s + k * WS_STRIDE + jcol;
        uint32_t* d2 = W2s + k * WS_STRIDE + jcol;
        d1[0] = cvt_tf32(v1.x); d1[1] = cvt_tf32(v1.y);
        d1[2] = cvt_tf32(v1.z); d1[3] = cvt_tf32(v1.w);
        d2[0] = cvt_tf32(v2.x); d2[1] = cvt_tf32(v2.y);
        d2[2] = cvt_tf32(v2.z); d2[3] = cvt_tf32(v2.w);
    }
    // ---- load X tile: cvt to tf32 once, store bits ----
#pragma unroll
    for (int i = 0; i < 8; i++) {
        int idx = tid + i * 256;            // [0,2048): 128 rows x 16 float4
        int nl = idx >> 4;
        int k4 = idx & 15;
        int node = tile + nl;
        if (node > N_NODES - 1) node = N_NODES - 1;
        float4 v = __ldg((const float4*)(embeds + (size_t)node * H) + k4);
        uint32_t* d = Xs + nl * XS_STRIDE + k4 * 4;
        d[0] = cvt_tf32(v.x); d[1] = cvt_tf32(v.y);
        d[2] = cvt_tf32(v.z); d[3] = cvt_tf32(v.w);
    }
    __syncthreads();

    const uint32_t* xw = Xs + warp * 16 * XS_STRIDE;
    const int q8 = q * 8;

    float C[8][4];
    float p1lo, p1hi, p2lo, p2hi;

    // ================= pass A: X @ W1 =================
#pragma unroll
    for (int jt = 0; jt < 8; jt++)
#pragma unroll
        for (int r = 0; r < 4; r++) C[jt][r] = 0.f;

#pragma unroll
    for (int kk = 0; kk < 8; kk++) {
        int kb = kk * 8;
        uint32_t A[4];
        A[0] = xw[g * XS_STRIDE + kb + q];
        A[1] = xw[(g + 8) * XS_STRIDE + kb + q];
        A[2] = xw[g * XS_STRIDE + kb + q + 4];
        A[3] = xw[(g + 8) * XS_STRIDE + kb + q + 4];
        const uint32_t* wk0 = W1s + (kb + q) * WS_STRIDE;
        const uint32_t* wk4 = W1s + (kb + q + 4) * WS_STRIDE;
#pragma unroll
        for (int jt = 0; jt < 8; jt++) {
            int jb = (jt * 8 + g) ^ q8;      // unswizzle
            mma_tf32(C[jt], A, wk0[jb], wk4[jb]);
        }
    }
    {
        float slo = 0.f, shi = 0.f;
#pragma unroll
        for (int jt = 0; jt < 8; jt++) {
            int c0 = jt * 8 + q * 2;
            float bb0 = __ldg(b1 + c0),    bb1 = __ldg(b1 + c0 + 1);
            float aw0 = __ldg(att_w + c0), aw1 = __ldg(att_w + c0 + 1);
            slo += fmaxf(C[jt][0] + bb0, 0.f) * aw0 + fmaxf(C[jt][1] + bb1, 0.f) * aw1;
            shi += fmaxf(C[jt][2] + bb0, 0.f) * aw0 + fmaxf(C[jt][3] + bb1, 0.f) * aw1;
        }
        p1lo = slo; p1hi = shi;
    }

    // ================= pass B: X @ W2 (reuse C) =================
#pragma unroll
    for (int jt = 0; jt < 8; jt++)
#pragma unroll
        for (int r = 0; r < 4; r++) C[jt][r] = 0.f;

#pragma unroll
    for (int kk = 0; kk < 8; kk++) {
        int kb = kk * 8;
        uint32_t A[4];
        A[0] = xw[g * XS_STRIDE + kb + q];
        A[1] = xw[(g + 8) * XS_STRIDE + kb + q];
        A[2] = xw[g * XS_STRIDE + kb + q + 4];
        A[3] = xw[(g + 8) * XS_STRIDE + kb + q + 4];
        const uint32_t* wk0 = W2s + (kb + q) * WS_STRIDE;
        const uint32_t* wk4 = W2s + (kb + q + 4) * WS_STRIDE;
#pragma unroll
        for (int jt = 0; jt < 8; jt++) {
            int jb = (jt * 8 + g) ^ q8;
            mma_tf32(C[jt], A, wk0[jb], wk4[jb]);
        }
    }
    {
        float slo = 0.f, shi = 0.f;
#pragma unroll
        for (int jt = 0; jt < 8; jt++) {
            int c0 = jt * 8 + q * 2;
            float bb0 = __ldg(b2 + c0),        bb1 = __ldg(b2 + c0 + 1);
            float aw0 = __ldg(att_w + H + c0), aw1 = __ldg(att_w + H + c0 + 1);
            slo += fmaxf(C[jt][0] + bb0, 0.f) * aw0 + fmaxf(C[jt][1] + bb1, 0.f) * aw1;
            shi += fmaxf(C[jt][2] + bb0, 0.f) * aw0 + fmaxf(C[jt][3] + bb1, 0.f) * aw1;
        }
        p2lo = slo; p2hi = shi;
    }

    // ---- quad reduce + write ----
#pragma unroll
    for (int m = 1; m <= 2; m <<= 1) {
        p1lo += __shfl_xor_sync(0xffffffffu, p1lo, m);
        p1hi += __shfl_xor_sync(0xffffffffu, p1hi, m);
        p2lo += __shfl_xor_sync(0xffffffffu, p2lo, m);
        p2hi += __shfl_xor_sync(0xffffffffu, p2hi, m);
    }

    if (q == 0) {
        float ab = __ldg(att_b);
        int node = tile + warp * 16 + g;
        if (node < N_NODES) {
            g_s1[node] = p1lo;
            g_s2[node] = p2lo + ab;
        }
        if (node + 8 < N_NODES) {
            g_s1[node + 8] = p1hi;
            g_s2[node + 8] = p2hi + ab;
        }
    }

    if (tid < 128) {
        int node = tile + tid;
        if (node < N_NODES) g_rowsum[node] = 0.f;
    }
}

// ------------------------------------------------------------------------
// Kernel 2: per-edge exp(att) + segment-sum; also zeroes out_part
// (exactly one float4 per thread: 800k threads x 4 = 3.2M floats = N*H).
// ------------------------------------------------------------------------
__global__ __launch_bounds__(256)
void gat_edge_att_kernel(const int* __restrict__ edge_index,
                         float* __restrict__ out_part) {
    int e = blockIdx.x * blockDim.x + threadIdx.x;
    if (e >= N_EDGES) return;

    ((float4*)out_part)[e] = make_float4(0.f, 0.f, 0.f, 0.f);

    int r = __ldg(edge_index + e);
    int c = __ldg(edge_index + N_EDGES + e);
    float ea = __expf(__ldg(g_s1 + r) + __ldg(g_s2 + c));
    g_expatt[e] = ea;
    atomicAdd(&g_rowsum[r], ea);
}

// ------------------------------------------------------------------------
// Kernel 3: per-edge value + SpMM scatter (16 threads/edge, float4 red).
// ------------------------------------------------------------------------
__global__ __launch_bounds__(256)
void gat_edge_spmm_kernel(const int* __restrict__ edge_index,
                          const float* __restrict__ adj_values,
                          const float* __restrict__ embeds,
                          float* __restrict__ values,
                          float* __restrict__ out_part) {
    unsigned gid = blockIdx.x * blockDim.x + threadIdx.x;
    unsigned e = gid >> 4;
    if (e >= N_EDGES) return;
    unsigned sub = gid & 15u;

    int r = __ldg(edge_index + e);
    int c = __ldg(edge_index + N_EDGES + e);
    float ea = __ldg(g_expatt + e);
    float rs = __ldg(g_rowsum + r) + 1e-6f;
    float v = fmaf(RES, __ldg(adj_values + e), __fdividef(ea, rs)) * INV_1PRES;
    if (sub == 0) values[e] = v;

    float4 ev = __ldg((const float4*)(embeds + (size_t)c * H + sub * 4));
    float* dst = out_part + (size_t)r * H + sub * 4;
    asm volatile("red.global.add.v4.f32 [%0], {%1, %2, %3, %4};"
                 :: "l"(dst), "f"(ev.x * v), "f"(ev.y * v), "f"(ev.z * v), "f"(ev.w * v)
                 : "memory");
}

// ------------------------------------------------------------------------
extern "C" void kernel_launch(void* const* d_in, const int* in_sizes, int n_in,
                              void* d_out, int out_size) {
    const int*   edge_index = (const int*)d_in[0];
    const float* adj_values = (const float*)d_in[1];
    const float* embeds     = (const float*)d_in[2];
    const float* W1         = (const float*)d_in[3];
    const float* b1         = (const float*)d_in[4];
    const float* W2         = (const float*)d_in[5];
    const float* b2         = (const float*)d_in[6];
    const float* att_w      = (const float*)d_in[7];
    const float* att_b      = (const float*)d_in[8];

    float* values   = (float*)d_out;            // [E]
    float* out_part = (float*)d_out + N_EDGES;  // [N, H]

    const int smem_bytes = (128 * XS_STRIDE + 2 * 64 * WS_STRIDE) * 4;  // 67584

    static bool attr_done = false;
    if (!attr_done) {
        cudaFuncSetAttribute(gat_node_kernel,
                             cudaFuncAttributeMaxDynamicSharedMemorySize, smem_bytes);
        attr_done = true;
    }

    gat_node_kernel<<<(N_NODES + 127) / 128, 256, smem_bytes>>>(
        embeds, W1, b1, W2, b2, att_w, att_b);

    gat_edge_att_kernel<<<(N_EDGES + 255) / 256, 256>>>(edge_index, out_part);

    gat_edge_spmm_kernel<<<(N_EDGES * 16 + 255) / 256, 256>>>(
        edge_index, adj_values, embeds, values, out_part);
}